// round 9
// baseline (speedup 1.0000x reference)
#include <cuda_runtime.h>
#include <cstdint>

#define BB 2
#define SS 4096
#define DD 128
#define HALF 64
#define TM 64            // rows per CTA (both kernels)
#define KU 192           // key union per tile
#define NT 256           // 8 warps

// Q/K/V scratch as tf32 bit patterns (Q pre-scaled by 1/sqrt(D))
__device__ uint32_t g_q[BB * SS * DD];
__device__ uint32_t g_k[BB * SS * DD];
__device__ uint32_t g_v[BB * SS * DD];

__device__ __forceinline__ uint32_t f2tf32(float f) {
    uint32_t u;
    asm("cvt.rna.tf32.f32 %0, %1;" : "=r"(u) : "f"(f));
    return u;
}
__device__ __forceinline__ uint32_t smem_u32(const void* p) {
    uint32_t a;
    asm("{ .reg .u64 t; cvta.to.shared.u64 t, %1; cvt.u32.u64 %0, t; }" : "=r"(a) : "l"(p));
    return a;
}
// 16B async copy, src_size<16 zero-fills
__device__ __forceinline__ void cpa(uint32_t dst, const void* src, int srcsz) {
    asm volatile("cp.async.cg.shared.global [%0], [%1], 16, %2;"
                 :: "r"(dst), "l"(src), "r"(srcsz) : "memory");
}
#define CP_COMMIT() asm volatile("cp.async.commit_group;" ::: "memory")
#define CP_WAIT(n)  asm volatile("cp.async.wait_group %0;" :: "n"(n) : "memory")

// D += A*B  (m16n8k8, tf32, row.col)
__device__ __forceinline__ void mma8(float* c, const uint32_t* a, uint32_t b0, uint32_t b1) {
    asm volatile(
        "mma.sync.aligned.m16n8k8.row.col.f32.tf32.tf32.f32 "
        "{%0,%1,%2,%3}, {%4,%5,%6,%7}, {%8,%9}, {%0,%1,%2,%3};"
        : "+f"(c[0]), "+f"(c[1]), "+f"(c[2]), "+f"(c[3])
        : "r"(a[0]), "r"(a[1]), "r"(a[2]), "r"(a[3]), "r"(b0), "r"(b1));
}

// smem pitches (words): A-pattern pitch%32==4 (132,196), B-pattern pitch%32==8 (136)
#define XP 132
#define WP 136
#define PP 196

// in-place fp32 -> tf32-bits conversion (rows x 128 cols, vectorized)
__device__ __forceinline__ void cvt_region(uint32_t* s, int pitch, int nrows, int tid) {
    for (int i = tid; i < nrows * 32; i += NT) {
        int r = i >> 5, c4 = (i & 31) << 2;
        float4 v = *(const float4*)&s[r * pitch + c4];
        uint4 u;
        u.x = f2tf32(v.x); u.y = f2tf32(v.y); u.z = f2tf32(v.z); u.w = f2tf32(v.w);
        *(uint4*)&s[r * pitch + c4] = u;
    }
}

// ---------------------------------------------------------------------------
// Kernel 1: QKV projection, W double-buffered, hoisted cvt. grid=128, 256 thr.
// warp tile: m16 x n64
// ---------------------------------------------------------------------------
#define QXS_W (TM * XP)       // 8448
#define QWS_W (DD * WP)       // 17408
#define QKV_SMEM ((QXS_W + 2 * QWS_W) * 4)   // 173056

__global__ __launch_bounds__(NT, 1) void qkv_kernel(
    const float* __restrict__ x,
    const float* __restrict__ Wq, const float* __restrict__ bq,
    const float* __restrict__ Wk, const float* __restrict__ bk,
    const float* __restrict__ Wv, const float* __restrict__ bv)
{
    extern __shared__ uint32_t smem[];
    uint32_t* Xs  = smem;               // [64][XP]
    uint32_t* WsA = smem + QXS_W;       // [128][WP]
    uint32_t* WsB = WsA + QWS_W;

    const uint32_t sb   = smem_u32(smem);
    const uint32_t xs_b = sb;
    const uint32_t wsA  = sb + QXS_W * 4;
    const uint32_t wsB  = wsA + QWS_W * 4;

    const int tid = threadIdx.x, w = tid >> 5, lane = tid & 31;
    const int gy = lane >> 2, gx = lane & 3;
    const int m0 = blockIdx.x * TM;
    const int r0 = 16 * (w & 3);
    const int c0 = 64 * (w >> 2);

    for (int i = tid; i < TM * 32; i += NT) {
        int m = i >> 5, c = (i & 31) << 2;
        cpa(xs_b + (uint32_t)(m * XP + c) * 4, &x[(m0 + m) * DD + c], 16);
    }
    for (int i = tid; i < DD * 32; i += NT) {
        int d = i >> 5, c = (i & 31) << 2;
        cpa(wsA + (uint32_t)(d * WP + c) * 4, &Wq[d * DD + c], 16);
    }
    CP_COMMIT();
    for (int i = tid; i < DD * 32; i += NT) {
        int d = i >> 5, c = (i & 31) << 2;
        cpa(wsB + (uint32_t)(d * WP + c) * 4, &Wk[d * DD + c], 16);
    }
    CP_COMMIT();
    CP_WAIT(1);
    __syncthreads();
    cvt_region(Xs, XP, TM, tid);
    cvt_region(WsA, WP, DD, tid);
    __syncthreads();

    const float scale = 0.088388347648318447f;  // 1/sqrt(128)

    auto run_mma = [&](const uint32_t* Wf, float acc[8][4]) {
        #pragma unroll
        for (int t = 0; t < 8; t++)
            #pragma unroll
            for (int c = 0; c < 4; c++) acc[t][c] = 0.f;
        #pragma unroll
        for (int ks = 0; ks < 16; ks++) {
            const int k0 = 8 * ks;
            uint32_t a[4];
            a[0] = Xs[(r0 + gy) * XP + k0 + gx];
            a[1] = Xs[(r0 + gy + 8) * XP + k0 + gx];
            a[2] = Xs[(r0 + gy) * XP + k0 + gx + 4];
            a[3] = Xs[(r0 + gy + 8) * XP + k0 + gx + 4];
            #pragma unroll
            for (int t = 0; t < 8; t++) {
                int n0 = c0 + 8 * t;
                uint32_t b0 = Wf[(k0 + gx) * WP + n0 + gy];
                uint32_t b1 = Wf[(k0 + gx + 4) * WP + n0 + gy];
                mma8(acc[t], a, b0, b1);
            }
        }
    };
    auto store_r = [&](uint32_t* dst, const float* bias, float scl, float acc[8][4]) {
        #pragma unroll
        for (int t = 0; t < 8; t++) {
            int col = c0 + 8 * t + 2 * gx;
            float bx = bias[col], by = bias[col + 1];
            uint2 v0 = make_uint2(f2tf32((acc[t][0] + bx) * scl), f2tf32((acc[t][1] + by) * scl));
            uint2 v1 = make_uint2(f2tf32((acc[t][2] + bx) * scl), f2tf32((acc[t][3] + by) * scl));
            *(uint2*)&dst[(size_t)(m0 + r0 + gy) * DD + col]     = v0;
            *(uint2*)&dst[(size_t)(m0 + r0 + gy + 8) * DD + col] = v1;
        }
    };

    float acc[8][4];
    run_mma(WsA, acc);               // Q  (Wk streaming behind)
    store_r(g_q, bq, scale, acc);

    CP_WAIT(0);                      // Wk landed
    __syncthreads();                 // all warps done reading WsA
    for (int i = tid; i < DD * 32; i += NT) {
        int d = i >> 5, c = (i & 31) << 2;
        cpa(wsA + (uint32_t)(d * WP + c) * 4, &Wv[d * DD + c], 16);
    }
    CP_COMMIT();
    cvt_region(WsB, WP, DD, tid);
    __syncthreads();

    run_mma(WsB, acc);               // K  (Wv streaming behind)
    store_r(g_k, bk, 1.f, acc);

    CP_WAIT(0);
    __syncthreads();
    cvt_region(WsA, WP, DD, tid);
    __syncthreads();

    run_mma(WsA, acc);               // V
    store_r(g_v, bv, 1.f, acc);
}

// ---------------------------------------------------------------------------
// Kernel 2: sliding-window attention. grid=128, 256 threads.
// MMA1 m16xn96/warp; exp+mask in registers; rowsum via shfl+smem atomics;
// MMA2 m16xn64/warp with 1/rowsum folded into the output.
// ---------------------------------------------------------------------------
#define AQS_W (TM * XP)       // 8448
#define AKV_W (KU * WP)       // 26112 (K at pitch XP, then V at pitch WP)
#define APS_W (TM * PP)       // 12544
#define ARS_W 64              // row sums
#define ATTN_SMEM ((AQS_W + AKV_W + APS_W + ARS_W) * 4)

__global__ __launch_bounds__(NT, 1) void attn_kernel(float* __restrict__ out)
{
    extern __shared__ uint32_t smem[];
    const uint32_t* Qs = smem;                         // [64][XP]
    const uint32_t* KV = smem + AQS_W;                 // K:[192][XP] / V:[192][WP]
    uint32_t*       Pu = smem + AQS_W + AKV_W;         // [64][PP] tf32 bits of exp(s)
    float*          rowsum = (float*)(smem + AQS_W + AKV_W + APS_W);

    const uint32_t sb   = smem_u32(smem);
    const uint32_t qs_b = sb;
    const uint32_t kv_b = sb + AQS_W * 4;

    const int tid = threadIdx.x, w = tid >> 5, lane = tid & 31;
    const int gy = lane >> 2, gx = lane & 3;
    const int b  = blockIdx.x >> 6;
    const int q0 = (blockIdx.x & 63) * TM;
    const int kb = q0 - HALF;

    const uint32_t* qg = g_q + (size_t)b * SS * DD;
    const uint32_t* kg = g_k + (size_t)b * SS * DD;
    const uint32_t* vg = g_v + (size_t)b * SS * DD;

    if (tid < TM) rowsum[tid] = 0.f;

    // stage Q + K (zero-fill OOB rows)
    for (int i = tid; i < TM * 32; i += NT) {
        int m = i >> 5, c = (i & 31) << 2;
        cpa(qs_b + (uint32_t)(m * XP + c) * 4, &qg[(q0 + m) * DD + c], 16);
    }
    for (int i = tid; i < KU * 32; i += NT) {
        int j = i >> 5, c = (i & 31) << 2;
        int key = kb + j;
        int ok = (key >= 0 && key < SS);
        cpa(kv_b + (uint32_t)(j * XP + c) * 4, &kg[(size_t)(ok ? key : 0) * DD + c], ok ? 16 : 0);
    }
    CP_COMMIT();
    CP_WAIT(0);
    __syncthreads();

    // ---- S = Q @ K^T : warp = m16 x n96 (12 tiles) ----
    const int r0 = 16 * (w & 3);
    const int cb = 96 * (w >> 2);
    {
        float sacc[12][4];
        #pragma unroll
        for (int t = 0; t < 12; t++)
            #pragma unroll
            for (int c = 0; c < 4; c++) sacc[t][c] = 0.f;

        #pragma unroll
        for (int ks = 0; ks < 16; ks++) {
            const int k0 = 8 * ks;
            uint32_t a[4];
            a[0] = Qs[(r0 + gy) * XP + k0 + gx];
            a[1] = Qs[(r0 + gy + 8) * XP + k0 + gx];
            a[2] = Qs[(r0 + gy) * XP + k0 + gx + 4];
            a[3] = Qs[(r0 + gy + 8) * XP + k0 + gx + 4];
            #pragma unroll
            for (int t = 0; t < 12; t++) {
                int n0 = cb + 8 * t;
                uint32_t b0 = KV[(n0 + gy) * XP + k0 + gx];
                uint32_t b1 = KV[(n0 + gy) * XP + k0 + gx + 4];
                mma8(sacc[t], a, b0, b1);
            }
        }

        // mask + exp in registers; write tf32 bits of p; reduce row sums
        float part[2] = {0.f, 0.f};
        #pragma unroll
        for (int t = 0; t < 12; t++) {
            #pragma unroll
            for (int h = 0; h < 2; h++) {
                int q = r0 + gy + 8 * h;
                int j0 = cb + 8 * t + 2 * gx;
                float p0 = 0.f, p1 = 0.f;
                {
                    int j = j0, key = kb + j, dj = j - q;
                    if (dj >= 0 && dj <= 2 * HALF && key >= 0 && key < SS)
                        p0 = __expf(sacc[t][2 * h]);
                }
                {
                    int j = j0 + 1, key = kb + j, dj = j - q;
                    if (dj >= 0 && dj <= 2 * HALF && key >= 0 && key < SS)
                        p1 = __expf(sacc[t][2 * h + 1]);
                }
                part[h] += p0 + p1;
                *(uint2*)&Pu[q * PP + j0] = make_uint2(f2tf32(p0), f2tf32(p1));
            }
        }
        // quad reduce over gx lanes (same row)
        #pragma unroll
        for (int h = 0; h < 2; h++) {
            part[h] += __shfl_xor_sync(0xffffffffu, part[h], 1);
            part[h] += __shfl_xor_sync(0xffffffffu, part[h], 2);
        }
        if (gx == 0) {
            atomicAdd(&rowsum[r0 + gy], part[0]);
            atomicAdd(&rowsum[r0 + gy + 8], part[1]);
        }
    }
    __syncthreads();          // P + rowsums complete; all KV reads done

    // ---- V copy (overwrites K buffer) ----
    for (int i = tid; i < KU * 32; i += NT) {
        int j = i >> 5, c = (i & 31) << 2;
        int key = kb + j;
        int ok = (key >= 0 && key < SS);
        cpa(kv_b + (uint32_t)(j * WP + c) * 4, &vg[(size_t)(ok ? key : 0) * DD + c], ok ? 16 : 0);
    }
    CP_COMMIT();
    CP_WAIT(0);
    __syncthreads();

    // ---- O = (P @ V) * inv[row] : warp = m16 x n64, 24 k-steps ----
    {
        const int d0 = 64 * (w >> 2);
        float oacc[8][4];
        #pragma unroll
        for (int t = 0; t < 8; t++)
            #pragma unroll
            for (int c = 0; c < 4; c++) oacc[t][c] = 0.f;

        #pragma unroll
        for (int ks = 0; ks < 24; ks++) {
            const int k0 = 8 * ks;
            uint32_t a[4];
            a[0] = Pu[(r0 + gy) * PP + k0 + gx];
            a[1] = Pu[(r0 + gy + 8) * PP + k0 + gx];
            a[2] = Pu[(r0 + gy) * PP + k0 + gx + 4];
            a[3] = Pu[(r0 + gy + 8) * PP + k0 + gx + 4];
            #pragma unroll
            for (int t = 0; t < 8; t++) {
                int n0 = d0 + 8 * t;
                uint32_t b0 = KV[(k0 + gx) * WP + n0 + gy];
                uint32_t b1 = KV[(k0 + gx + 4) * WP + n0 + gy];
                mma8(oacc[t], a, b0, b1);
            }
        }

        const float inv0 = 1.f / rowsum[r0 + gy];
        const float inv1 = 1.f / rowsum[r0 + gy + 8];
        float* ob = out + (size_t)(b * SS + q0) * DD;
        #pragma unroll
        for (int t = 0; t < 8; t++) {
            int col = d0 + 8 * t + 2 * gx;
            *(float2*)&ob[(r0 + gy) * DD + col]     = make_float2(oacc[t][0] * inv0, oacc[t][1] * inv0);
            *(float2*)&ob[(r0 + gy + 8) * DD + col] = make_float2(oacc[t][2] * inv1, oacc[t][3] * inv1);
        }
    }
}

// ---------------------------------------------------------------------------
extern "C" void kernel_launch(void* const* d_in, const int* in_sizes, int n_in,
                              void* d_out, int out_size)
{
    const float* x  = (const float*)d_in[0];
    const float* Wq = (const float*)d_in[1];
    const float* bq = (const float*)d_in[2];
    const float* Wk = (const float*)d_in[3];
    const float* bk = (const float*)d_in[4];
    const float* Wv = (const float*)d_in[5];
    const float* bv = (const float*)d_in[6];
    float* out = (float*)d_out;

    cudaFuncSetAttribute(qkv_kernel,  cudaFuncAttributeMaxDynamicSharedMemorySize, QKV_SMEM);
    cudaFuncSetAttribute(attn_kernel, cudaFuncAttributeMaxDynamicSharedMemorySize, ATTN_SMEM);

    qkv_kernel<<<(BB * SS) / TM, NT, QKV_SMEM>>>(x, Wq, bq, Wk, bk, Wv, bv);
    attn_kernel<<<BB * (SS / TM), NT, ATTN_SMEM>>>(out);
}

// round 11
// speedup vs baseline: 1.3258x; 1.3258x over previous
#include <cuda_runtime.h>
#include <cstdint>

#define BB 2
#define SS 4096
#define DD 128
#define HALF 64
#define TM 64            // rows per CTA (both kernels)
#define KU 192           // key union per tile
#define NT 256           // 8 warps

// Q/K/V scratch as tf32 bit patterns (Q pre-scaled by 1/sqrt(D))
__device__ uint32_t g_q[BB * SS * DD];
__device__ uint32_t g_k[BB * SS * DD];
__device__ uint32_t g_v[BB * SS * DD];

__device__ __forceinline__ uint32_t f2tf32(float f) {
    uint32_t u;
    asm("cvt.rna.tf32.f32 %0, %1;" : "=r"(u) : "f"(f));
    return u;
}
__device__ __forceinline__ uint32_t smem_u32(const void* p) {
    uint32_t a;
    asm("{ .reg .u64 t; cvta.to.shared.u64 t, %1; cvt.u32.u64 %0, t; }" : "=r"(a) : "l"(p));
    return a;
}
// 16B async copy, src_size<16 zero-fills
__device__ __forceinline__ void cpa(uint32_t dst, const void* src, int srcsz) {
    asm volatile("cp.async.cg.shared.global [%0], [%1], 16, %2;"
                 :: "r"(dst), "l"(src), "r"(srcsz) : "memory");
}
#define CP_COMMIT() asm volatile("cp.async.commit_group;" ::: "memory")
#define CP_WAIT(n)  asm volatile("cp.async.wait_group %0;" :: "n"(n) : "memory")

// D += A*B  (m16n8k8, tf32, row.col)
__device__ __forceinline__ void mma8(float* c, const uint32_t* a, uint32_t b0, uint32_t b1) {
    asm volatile(
        "mma.sync.aligned.m16n8k8.row.col.f32.tf32.tf32.f32 "
        "{%0,%1,%2,%3}, {%4,%5,%6,%7}, {%8,%9}, {%0,%1,%2,%3};"
        : "+f"(c[0]), "+f"(c[1]), "+f"(c[2]), "+f"(c[3])
        : "r"(a[0]), "r"(a[1]), "r"(a[2]), "r"(a[3]), "r"(b0), "r"(b1));
}

// smem pitches (words): A-pattern pitch%32==4 (132,196), B-pattern pitch%32==8 (136)
#define XP 132
#define WP 136
#define PP 196

// ---------------------------------------------------------------------------
// Kernel 1: QKV projection, W double-buffered, A-frags cached in registers.
// grid=128, 256 threads. warp tile m16 x n64.
// ---------------------------------------------------------------------------
#define QXS_W (TM * XP)       // 8448
#define QWS_W (DD * WP)       // 17408
#define QKV_SMEM ((QXS_W + 2 * QWS_W) * 4)   // 173056

__global__ __launch_bounds__(NT, 1) void qkv_kernel(
    const float* __restrict__ x,
    const float* __restrict__ Wq, const float* __restrict__ bq,
    const float* __restrict__ Wk, const float* __restrict__ bk,
    const float* __restrict__ Wv, const float* __restrict__ bv)
{
    extern __shared__ uint32_t smem[];
    const float* Xs  = (const float*)smem;          // [64][XP] fp32
    const float* WsA = (const float*)(smem + QXS_W);// [128][WP] fp32
    const float* WsB = WsA + QWS_W;

    const uint32_t sb   = smem_u32(smem);
    const uint32_t xs_b = sb;
    const uint32_t wsA  = sb + QXS_W * 4;
    const uint32_t wsB  = wsA + QWS_W * 4;

    const int tid = threadIdx.x, w = tid >> 5, lane = tid & 31;
    const int gy = lane >> 2, gx = lane & 3;
    const int m0 = blockIdx.x * TM;
    const int r0 = 16 * (w & 3);
    const int c0 = 64 * (w >> 2);

    // group0: X + Wq ; group1: Wk
    for (int i = tid; i < TM * 32; i += NT) {
        int m = i >> 5, c = (i & 31) << 2;
        cpa(xs_b + (uint32_t)(m * XP + c) * 4, &x[(m0 + m) * DD + c], 16);
    }
    for (int i = tid; i < DD * 32; i += NT) {
        int d = i >> 5, c = (i & 31) << 2;
        cpa(wsA + (uint32_t)(d * WP + c) * 4, &Wq[d * DD + c], 16);
    }
    CP_COMMIT();
    for (int i = tid; i < DD * 32; i += NT) {
        int d = i >> 5, c = (i & 31) << 2;
        cpa(wsB + (uint32_t)(d * WP + c) * 4, &Wk[d * DD + c], 16);
    }
    CP_COMMIT();
    CP_WAIT(1);
    __syncthreads();

    // cache A fragments in registers (converted once, reused for Q/K/V)
    uint32_t a_all[16][4];
    #pragma unroll
    for (int ks = 0; ks < 16; ks++) {
        const int k0 = 8 * ks;
        a_all[ks][0] = f2tf32(Xs[(r0 + gy) * XP + k0 + gx]);
        a_all[ks][1] = f2tf32(Xs[(r0 + gy + 8) * XP + k0 + gx]);
        a_all[ks][2] = f2tf32(Xs[(r0 + gy) * XP + k0 + gx + 4]);
        a_all[ks][3] = f2tf32(Xs[(r0 + gy + 8) * XP + k0 + gx + 4]);
    }

    const float scale = 0.088388347648318447f;  // 1/sqrt(128)

    auto run_mma = [&](const float* Wf, float acc[8][4]) {
        #pragma unroll
        for (int t = 0; t < 8; t++)
            #pragma unroll
            for (int c = 0; c < 4; c++) acc[t][c] = 0.f;
        #pragma unroll
        for (int ks = 0; ks < 16; ks++) {
            const int k0 = 8 * ks;
            #pragma unroll
            for (int t = 0; t < 8; t++) {
                int n0 = c0 + 8 * t;
                uint32_t b0 = f2tf32(Wf[(k0 + gx) * WP + n0 + gy]);
                uint32_t b1 = f2tf32(Wf[(k0 + gx + 4) * WP + n0 + gy]);
                mma8(acc[t], a_all[ks], b0, b1);
            }
        }
    };
    auto store_r = [&](uint32_t* dst, const float* bias, float scl, float acc[8][4]) {
        #pragma unroll
        for (int t = 0; t < 8; t++) {
            int col = c0 + 8 * t + 2 * gx;
            float bx = bias[col], by = bias[col + 1];
            uint2 v0 = make_uint2(f2tf32((acc[t][0] + bx) * scl), f2tf32((acc[t][1] + by) * scl));
            uint2 v1 = make_uint2(f2tf32((acc[t][2] + bx) * scl), f2tf32((acc[t][3] + by) * scl));
            *(uint2*)&dst[(size_t)(m0 + r0 + gy) * DD + col]     = v0;
            *(uint2*)&dst[(size_t)(m0 + r0 + gy + 8) * DD + col] = v1;
        }
    };

    float acc[8][4];
    run_mma(WsA, acc);               // Q  (Wk streaming behind)
    store_r(g_q, bq, scale, acc);

    CP_WAIT(0);                      // Wk landed
    __syncthreads();                 // all warps done reading WsA
    for (int i = tid; i < DD * 32; i += NT) {
        int d = i >> 5, c = (i & 31) << 2;
        cpa(wsA + (uint32_t)(d * WP + c) * 4, &Wv[d * DD + c], 16);
    }
    CP_COMMIT();

    run_mma(WsB, acc);               // K  (Wv streaming behind)
    store_r(g_k, bk, 1.f, acc);

    CP_WAIT(0);
    __syncthreads();

    run_mma(WsA, acc);               // V
    store_r(g_v, bv, 1.f, acc);
}

// ---------------------------------------------------------------------------
// Kernel 2: sliding-window attention, band-aware warp decomposition.
// grid=128, 256 threads. Row-group g = w&3 (rows [16g,16g+16)) has valid keys
// exactly [16g, 16g+144). MMA1: warp covers 72 of those cols (9 tiles).
// MMA2: only the 18 k-steps intersecting the band.
// ---------------------------------------------------------------------------
#define AQS_W (TM * XP)       // 8448
#define AKV_W (KU * WP)       // 26112 (K at pitch XP, then V at pitch WP)
#define APS_W (TM * PP)       // 12544
#define ARS_W 64              // row sums
#define ATTN_SMEM ((AQS_W + AKV_W + APS_W + ARS_W) * 4)

__global__ __launch_bounds__(NT, 1) void attn_kernel(float* __restrict__ out)
{
    extern __shared__ uint32_t smem[];
    const uint32_t* Qs = smem;                         // [64][XP]
    const uint32_t* KV = smem + AQS_W;                 // K:[192][XP] / V:[192][WP]
    uint32_t*       Pu = smem + AQS_W + AKV_W;         // [64][PP] tf32 bits of exp(s)
    float*          rowsum = (float*)(smem + AQS_W + AKV_W + APS_W);

    const uint32_t sb   = smem_u32(smem);
    const uint32_t qs_b = sb;
    const uint32_t kv_b = sb + AQS_W * 4;

    const int tid = threadIdx.x, w = tid >> 5, lane = tid & 31;
    const int gy = lane >> 2, gx = lane & 3;
    const int b  = blockIdx.x >> 6;
    const int q0 = (blockIdx.x & 63) * TM;
    const int kb = q0 - HALF;

    const uint32_t* qg = g_q + (size_t)b * SS * DD;
    const uint32_t* kg = g_k + (size_t)b * SS * DD;
    const uint32_t* vg = g_v + (size_t)b * SS * DD;

    if (tid < TM) rowsum[tid] = 0.f;

    // stage Q + K (zero-fill OOB rows)
    for (int i = tid; i < TM * 32; i += NT) {
        int m = i >> 5, c = (i & 31) << 2;
        cpa(qs_b + (uint32_t)(m * XP + c) * 4, &qg[(q0 + m) * DD + c], 16);
    }
    for (int i = tid; i < KU * 32; i += NT) {
        int j = i >> 5, c = (i & 31) << 2;
        int key = kb + j;
        int ok = (key >= 0 && key < SS);
        cpa(kv_b + (uint32_t)(j * XP + c) * 4, &kg[(size_t)(ok ? key : 0) * DD + c], ok ? 16 : 0);
    }
    CP_COMMIT();
    CP_WAIT(0);
    __syncthreads();

    const int r0   = 16 * (w & 3);          // row-group base
    const int half = w >> 2;                // band half (0/1)
    const int nb   = r0 + 72 * half;        // this warp's column base (9 tiles)

    // ---- S = Q @ K^T : warp = m16 x n72 over the valid band ----
    {
        float sacc[9][4];
        #pragma unroll
        for (int t = 0; t < 9; t++)
            #pragma unroll
            for (int c = 0; c < 4; c++) sacc[t][c] = 0.f;

        #pragma unroll
        for (int ks = 0; ks < 16; ks++) {
            const int k0 = 8 * ks;
            uint32_t a[4];
            a[0] = Qs[(r0 + gy) * XP + k0 + gx];
            a[1] = Qs[(r0 + gy + 8) * XP + k0 + gx];
            a[2] = Qs[(r0 + gy) * XP + k0 + gx + 4];
            a[3] = Qs[(r0 + gy + 8) * XP + k0 + gx + 4];
            #pragma unroll
            for (int t = 0; t < 9; t++) {
                int n0 = nb + 8 * t;
                uint32_t b0 = KV[(n0 + gy) * XP + k0 + gx];
                uint32_t b1 = KV[(n0 + gy) * XP + k0 + gx + 4];
                mma8(sacc[t], a, b0, b1);
            }
        }

        // mask + exp in registers; write tf32 bits of p; reduce row sums
        float part[2] = {0.f, 0.f};
        #pragma unroll
        for (int t = 0; t < 9; t++) {
            #pragma unroll
            for (int h = 0; h < 2; h++) {
                int q  = r0 + gy + 8 * h;
                int j0 = nb + 8 * t + 2 * gx;
                float p0 = 0.f, p1 = 0.f;
                {
                    int j = j0, key = kb + j, dj = j - q;
                    if (dj >= 0 && dj <= 2 * HALF && key >= 0 && key < SS)
                        p0 = __expf(sacc[t][2 * h]);
                }
                {
                    int j = j0 + 1, key = kb + j, dj = j - q;
                    if (dj >= 0 && dj <= 2 * HALF && key >= 0 && key < SS)
                        p1 = __expf(sacc[t][2 * h + 1]);
                }
                part[h] += p0 + p1;
                *(uint2*)&Pu[q * PP + j0] = make_uint2(f2tf32(p0), f2tf32(p1));
            }
        }
        #pragma unroll
        for (int h = 0; h < 2; h++) {
            part[h] += __shfl_xor_sync(0xffffffffu, part[h], 1);
            part[h] += __shfl_xor_sync(0xffffffffu, part[h], 2);
        }
        if (gx == 0) {
            atomicAdd(&rowsum[r0 + gy], part[0]);
            atomicAdd(&rowsum[r0 + gy + 8], part[1]);
        }
    }
    __syncthreads();          // P + rowsums complete; all KV reads done

    // ---- V copy (overwrites K buffer) ----
    for (int i = tid; i < KU * 32; i += NT) {
        int j = i >> 5, c = (i & 31) << 2;
        int key = kb + j;
        int ok = (key >= 0 && key < SS);
        cpa(kv_b + (uint32_t)(j * WP + c) * 4, &vg[(size_t)(ok ? key : 0) * DD + c], ok ? 16 : 0);
    }
    CP_COMMIT();
    CP_WAIT(0);
    __syncthreads();

    // ---- O = (P @ V) * inv[row] : warp = m16 x n64, 18 band k-steps ----
    {
        const int d0 = 64 * half;
        const int ksb = r0 >> 3;            // first k-tile intersecting the band
        float oacc[8][4];
        #pragma unroll
        for (int t = 0; t < 8; t++)
            #pragma unroll
            for (int c = 0; c < 4; c++) oacc[t][c] = 0.f;

        #pragma unroll
        for (int ks = 0; ks < 18; ks++) {
            const int k0 = 8 * (ksb + ks);
            uint32_t a[4];
            a[0] = Pu[(r0 + gy) * PP + k0 + gx];
            a[1] = Pu[(r0 + gy + 8) * PP + k0 + gx];
            a[2] = Pu[(r0 + gy) * PP + k0 + gx + 4];
            a[3] = Pu[(r0 + gy + 8) * PP + k0 + gx + 4];
            #pragma unroll
            for (int t = 0; t < 8; t++) {
                int n0 = d0 + 8 * t;
                uint32_t b0 = KV[(k0 + gx) * WP + n0 + gy];
                uint32_t b1 = KV[(k0 + gx + 4) * WP + n0 + gy];
                mma8(oacc[t], a, b0, b1);
            }
        }

        const float inv0 = 1.f / rowsum[r0 + gy];
        const float inv1 = 1.f / rowsum[r0 + gy + 8];
        float* ob = out + (size_t)(b * SS + q0) * DD;
        #pragma unroll
        for (int t = 0; t < 8; t++) {
            int col = d0 + 8 * t + 2 * gx;
            *(float2*)&ob[(r0 + gy) * DD + col]     = make_float2(oacc[t][0] * inv0, oacc[t][1] * inv0);
            *(float2*)&ob[(r0 + gy + 8) * DD + col] = make_float2(oacc[t][2] * inv1, oacc[t][3] * inv1);
        }
    }
}

// ---------------------------------------------------------------------------
extern "C" void kernel_launch(void* const* d_in, const int* in_sizes, int n_in,
                              void* d_out, int out_size)
{
    const float* x  = (const float*)d_in[0];
    const float* Wq = (const float*)d_in[1];
    const float* bq = (const float*)d_in[2];
    const float* Wk = (const float*)d_in[3];
    const float* bk = (const float*)d_in[4];
    const float* Wv = (const float*)d_in[5];
    const float* bv = (const float*)d_in[6];
    float* out = (float*)d_out;

    cudaFuncSetAttribute(qkv_kernel,  cudaFuncAttributeMaxDynamicSharedMemorySize, QKV_SMEM);
    cudaFuncSetAttribute(attn_kernel, cudaFuncAttributeMaxDynamicSharedMemorySize, ATTN_SMEM);

    qkv_kernel<<<(BB * SS) / TM, NT, QKV_SMEM>>>(x, Wq, bq, Wk, bk, Wv, bv);
    attn_kernel<<<BB * (SS / TM), NT, ATTN_SMEM>>>(out);
}